// round 2
// baseline (speedup 1.0000x reference)
#include <cuda_runtime.h>
#include <cstdint>
#include <cstddef>

// Problem constants
#define B_  4
#define S_  2048
#define NH_ 16
#define HD_ 64
#define HID_ 1024

// Scratch (device globals: allocation-free per harness rules)
// Q/K/V stored [b, h, s, d] for contiguous per-(b,h) attention.
__device__ float g_Q[(size_t)B_ * NH_ * S_ * HD_];
__device__ float g_K[(size_t)B_ * NH_ * S_ * HD_];
__device__ float g_V[(size_t)B_ * NH_ * S_ * HD_];
// ctx stored [b, s, hid] (h,d contiguous) ready for final GEMM.
__device__ float g_ctx[(size_t)B_ * S_ * HID_];

// ---------------------------------------------------------------------------
// Kernel 1: per-head QKV projection.
// grid (S/64, NH, B), 256 threads. Q gets the 1/sqrt(d)=1/8 temperature baked in.
// ---------------------------------------------------------------------------
__global__ void __launch_bounds__(256) qkv_kernel(const float* __restrict__ x,
                                                  const float* __restrict__ Wq,
                                                  const float* __restrict__ Wk,
                                                  const float* __restrict__ Wv) {
    __shared__ float xs[64 * 64];
    __shared__ float Ws[64 * 64];

    const int st = blockIdx.x, h = blockIdx.y, b = blockIdx.z;
    const int s0 = st * 64;
    const int t  = threadIdx.x;

    // Load x tile [64 rows of s][64 d] for this head.
    const float* xbase = x + ((size_t)(b * S_ + s0)) * HID_ + h * HD_;
    for (int i = t; i < 64 * 16; i += 256) {
        int row = i >> 4, c4 = (i & 15) * 4;
        *(float4*)(xs + row * 64 + c4) = *(const float4*)(xbase + (size_t)row * HID_ + c4);
    }

    const float* Wptr[3] = { Wq + (size_t)h * 4096, Wk + (size_t)h * 4096, Wv + (size_t)h * 4096 };
    const float  scl[3]  = { 0.125f, 1.0f, 1.0f };   // temperature folded into Q

    const int c  = t & 63;      // output column e
    const int ty = t >> 6;      // row group: rows ty*16 .. ty*16+15
    const size_t obase = ((size_t)(b * NH_ + h)) * S_ * HD_ + (size_t)s0 * HD_;

    __syncthreads();

    for (int m = 0; m < 3; m++) {
        for (int i = t; i < 64 * 16; i += 256) {
            int row = i >> 4, c4 = (i & 15) * 4;
            *(float4*)(Ws + row * 64 + c4) = *(const float4*)(Wptr[m] + row * 64 + c4);
        }
        __syncthreads();

        float* O = (m == 0) ? g_Q : (m == 1) ? g_K : g_V;
        const float sc = scl[m];
        #pragma unroll 4
        for (int rr = 0; rr < 16; rr++) {
            const int r = ty * 16 + rr;
            float acc = 0.0f;
            #pragma unroll
            for (int k = 0; k < 64; k++)
                acc = fmaf(xs[r * 64 + k], Ws[k * 64 + c], acc);
            O[obase + (size_t)r * HD_ + c] = acc * sc;
        }
        __syncthreads();
    }
}

// ---------------------------------------------------------------------------
// Kernel 2: flash-style attention with POST-softmax multiplicative mask.
// Denominator l sums exp over ALL keys; numerator gated by ~mask.
// grid (S/128, NH, B), 128 threads, one thread = one query row.
// Mask arrives as int32 (jax bool promoted by the harness).
// ---------------------------------------------------------------------------
__global__ void __launch_bounds__(128) attn_kernel(const int* __restrict__ mask) {
    __shared__ float Ks[64 * 64];
    __shared__ float Vs[64 * 64];

    const int qt = blockIdx.x, h = blockIdx.y, b = blockIdx.z;
    const int q0 = qt * 128;
    const int tid = threadIdx.x;          // query row within tile
    const size_t hb = ((size_t)(b * NH_ + h)) * S_ * HD_;

    // Load this thread's (pre-scaled) Q row into registers.
    float qreg[64];
    {
        const float* qrow = g_Q + hb + (size_t)(q0 + tid) * HD_;
        #pragma unroll
        for (int k4 = 0; k4 < 16; k4++) {
            float4 v = *(const float4*)(qrow + k4 * 4);
            qreg[k4 * 4 + 0] = v.x; qreg[k4 * 4 + 1] = v.y;
            qreg[k4 * 4 + 2] = v.z; qreg[k4 * 4 + 3] = v.w;
        }
    }

    float acc[64];
    #pragma unroll
    for (int d = 0; d < 64; d++) acc[d] = 0.0f;
    float mrun = -1e30f, l = 0.0f;

    const int* mrow = mask + ((size_t)(b * S_) + (q0 + tid)) * (size_t)S_;

    #pragma unroll 1
    for (int t0 = 0; t0 < S_; t0 += 64) {
        __syncthreads();   // previous tile fully consumed
        for (int i = tid; i < 64 * 16; i += 128) {
            int row = i >> 4, c4 = (i & 15) * 4;
            *(float4*)(Ks + row * 64 + c4) = *(const float4*)(g_K + hb + (size_t)(t0 + row) * HD_ + c4);
            *(float4*)(Vs + row * 64 + c4) = *(const float4*)(g_V + hb + (size_t)(t0 + row) * HD_ + c4);
        }
        __syncthreads();

        #pragma unroll 1
        for (int ch = 0; ch < 4; ch++) {
            const int tc0 = ch * 16;
            float s[16];
            #pragma unroll
            for (int j = 0; j < 16; j++) {
                const float* krow = Ks + (tc0 + j) * 64;
                float a = 0.0f;
                #pragma unroll
                for (int k4 = 0; k4 < 16; k4++) {
                    float4 kv = *(const float4*)(krow + k4 * 4);
                    a = fmaf(qreg[k4 * 4 + 0], kv.x, a);
                    a = fmaf(qreg[k4 * 4 + 1], kv.y, a);
                    a = fmaf(qreg[k4 * 4 + 2], kv.z, a);
                    a = fmaf(qreg[k4 * 4 + 3], kv.w, a);
                }
                s[j] = a;
            }
            float cmax = s[0];
            #pragma unroll
            for (int j = 1; j < 16; j++) cmax = fmaxf(cmax, s[j]);
            const float mnew  = fmaxf(mrun, cmax);
            const float scale = __expf(mrun - mnew);
            mrun = mnew;
            l *= scale;
            #pragma unroll
            for (int d = 0; d < 64; d++) acc[d] *= scale;

            // int32 mask: 16 keys -> 4x int4 loads (64B, aligned).
            int mv[16];
            #pragma unroll
            for (int g = 0; g < 4; g++) {
                int4 mk = *(const int4*)(mrow + t0 + tc0 + g * 4);
                mv[g * 4 + 0] = mk.x; mv[g * 4 + 1] = mk.y;
                mv[g * 4 + 2] = mk.z; mv[g * 4 + 3] = mk.w;
            }

            #pragma unroll
            for (int j = 0; j < 16; j++) {
                const float p = __expf(s[j] - mrun);
                l += p;                                   // denominator: ALL keys
                const float pm = (mv[j] != 0) ? 0.0f : p; // numerator: kept keys only
                const float* vrow = Vs + (tc0 + j) * 64;
                #pragma unroll
                for (int k4 = 0; k4 < 16; k4++) {
                    float4 vv = *(const float4*)(vrow + k4 * 4);
                    acc[k4 * 4 + 0] = fmaf(pm, vv.x, acc[k4 * 4 + 0]);
                    acc[k4 * 4 + 1] = fmaf(pm, vv.y, acc[k4 * 4 + 1]);
                    acc[k4 * 4 + 2] = fmaf(pm, vv.z, acc[k4 * 4 + 2]);
                    acc[k4 * 4 + 3] = fmaf(pm, vv.w, acc[k4 * 4 + 3]);
                }
            }
        }
    }

    const float inv = 1.0f / l;
    float* orow = g_ctx + ((size_t)(b * S_) + (q0 + tid)) * HID_ + h * HD_;
    #pragma unroll
    for (int d = 0; d < 64; d += 4) {
        float4 v = make_float4(acc[d] * inv, acc[d + 1] * inv, acc[d + 2] * inv, acc[d + 3] * inv);
        *(float4*)(orow + d) = v;
    }
}

// ---------------------------------------------------------------------------
// Kernel 3: output projection  out[8192,1024] = ctx @ Wo.
// Classic 128x128x8 SGEMM, 256 threads, 8x8 microtile.
// ---------------------------------------------------------------------------
__global__ void __launch_bounds__(256) oproj_kernel(const float* __restrict__ Wo,
                                                    float* __restrict__ out) {
    __shared__ float As[8][132];   // padded, transposed A tile
    __shared__ float Bs[8][128];

    const int bn = blockIdx.x * 128;
    const int bm = blockIdx.y * 128;
    const int t  = threadIdx.x;
    const int tx = t & 15, ty = t >> 4;

    float acc[8][8];
    #pragma unroll
    for (int i = 0; i < 8; i++)
        #pragma unroll
        for (int j = 0; j < 8; j++) acc[i][j] = 0.0f;

    #pragma unroll 1
    for (int k0 = 0; k0 < HID_; k0 += 8) {
        {   // A: 128x8 -> transposed into As[k][m]
            int row = t >> 1, c4 = (t & 1) * 4;
            float4 v = *(const float4*)(g_ctx + (size_t)(bm + row) * HID_ + k0 + c4);
            As[c4 + 0][row] = v.x; As[c4 + 1][row] = v.y;
            As[c4 + 2][row] = v.z; As[c4 + 3][row] = v.w;
        }
        {   // B: 8x128
            int row = t >> 5, c4 = (t & 31) * 4;
            *(float4*)(&Bs[row][c4]) = *(const float4*)(Wo + (size_t)(k0 + row) * HID_ + bn + c4);
        }
        __syncthreads();

        #pragma unroll
        for (int k = 0; k < 8; k++) {
            float a[8], bb[8];
            float4 a0 = *(const float4*)(&As[k][ty * 8]);
            float4 a1 = *(const float4*)(&As[k][ty * 8 + 4]);
            a[0]=a0.x; a[1]=a0.y; a[2]=a0.z; a[3]=a0.w;
            a[4]=a1.x; a[5]=a1.y; a[6]=a1.z; a[7]=a1.w;
            float4 b0 = *(const float4*)(&Bs[k][tx * 8]);
            float4 b1 = *(const float4*)(&Bs[k][tx * 8 + 4]);
            bb[0]=b0.x; bb[1]=b0.y; bb[2]=b0.z; bb[3]=b0.w;
            bb[4]=b1.x; bb[5]=b1.y; bb[6]=b1.z; bb[7]=b1.w;
            #pragma unroll
            for (int i = 0; i < 8; i++)
                #pragma unroll
                for (int j = 0; j < 8; j++)
                    acc[i][j] = fmaf(a[i], bb[j], acc[i][j]);
        }
        __syncthreads();
    }

    #pragma unroll
    for (int i = 0; i < 8; i++) {
        float* orow = out + (size_t)(bm + ty * 8 + i) * HID_ + bn + tx * 8;
        *(float4*)(orow)     = make_float4(acc[i][0], acc[i][1], acc[i][2], acc[i][3]);
        *(float4*)(orow + 4) = make_float4(acc[i][4], acc[i][5], acc[i][6], acc[i][7]);
    }
}

// ---------------------------------------------------------------------------
extern "C" void kernel_launch(void* const* d_in, const int* in_sizes, int n_in,
                              void* d_out, int out_size) {
    const float* x    = (const float*)d_in[0];
    const int*   mask = (const int*)d_in[1];   // jax bool promoted to int32 by harness
    const float* Wq   = (const float*)d_in[2];
    const float* Wk   = (const float*)d_in[3];
    const float* Wv   = (const float*)d_in[4];
    const float* Wo   = (const float*)d_in[5];
    float*       out  = (float*)d_out;

    qkv_kernel<<<dim3(S_ / 64, NH_, B_), 256>>>(x, Wq, Wk, Wv);
    attn_kernel<<<dim3(S_ / 128, NH_, B_), 128>>>(mask);
    oproj_kernel<<<dim3(HID_ / 128, (B_ * S_) / 128), 256>>>(Wo, out);
}